// round 8
// baseline (speedup 1.0000x reference)
#include <cuda_runtime.h>
#include <cstdint>

#define N_NODES 100000
#define N_EDGES 3200000
#define F_IN    300
#define HID     32
#define NCLS    10

#define SCAN_B  512
#define SCAN_NBLK ((N_NODES + SCAN_B - 1) / SCAN_B)   // 196

#define GB_ROWS 256     // gemm1 rows per block
#define GKT     20      // gemm1 k-tile

// ---------------- scratch (device globals: no allocation allowed) ----------
__device__ int    g_is32;
__device__ int    g_ecnt[N_NODES];
__device__ int    g_off [N_NODES];
__device__ int    g_cur [N_NODES];
__device__ int    g_bsum[SCAN_NBLK];
__device__ int    g_bpre[SCAN_NBLK];
__device__ float  g_dinv[N_NODES];
__device__ int2   g_csr [N_EDGES];               // {src, norm-as-int} 25.6 MB
__device__ float4 g_h1  [N_NODES * (HID / 4)];   // 12.8 MB
__device__ float4 g_h2  [N_NODES * 3];           // 4.8 MB (10 -> 12 padded)

__device__ __forceinline__ float tanh_fast(float x) {
    float y;
    asm("tanh.approx.f32 %0, %1;" : "=f"(y) : "f"(x));
    return y;
}

// ---------------- detect dtype + zero histogram (fused) --------------------
__global__ void k_detect_zero(const unsigned long long* __restrict__ ei) {
    int i = blockIdx.x * blockDim.x + threadIdx.x;
    if (i < N_NODES) g_ecnt[i] = 0;
    if (blockIdx.x == 0) {
        unsigned long long v = ei[threadIdx.x];
        int any = __syncthreads_or(v > 0xFFFFFFFFull ? 1 : 0);
        if (threadIdx.x == 0) g_is32 = any;
    }
}

__global__ void k_hist(const void* __restrict__ ei) {
    int e = blockIdx.x * blockDim.x + threadIdx.x;
    int d = g_is32 ? ((const int*)ei)[N_EDGES + e]
                   : (int)((const long long*)ei)[N_EDGES + e];
    atomicAdd(&g_ecnt[d], 1);
}

// ---------------- 3-kernel exclusive scan ----------------------------------
__global__ void k_scan_reduce() {
    __shared__ int s[SCAN_B];
    int i = blockIdx.x * SCAN_B + threadIdx.x;
    s[threadIdx.x] = (i < N_NODES) ? g_ecnt[i] : 0;
    __syncthreads();
    for (int d = SCAN_B / 2; d > 0; d >>= 1) {
        if (threadIdx.x < d) s[threadIdx.x] += s[threadIdx.x + d];
        __syncthreads();
    }
    if (threadIdx.x == 0) g_bsum[blockIdx.x] = s[0];
}

__global__ void k_scan_mid() {
    int run = 0;
    for (int b = 0; b < SCAN_NBLK; b++) { g_bpre[b] = run; run += g_bsum[b]; }
}

__global__ void k_scan_write() {
    __shared__ int s[SCAN_B];
    int t = threadIdx.x;
    int i = blockIdx.x * SCAN_B + t;
    int v = (i < N_NODES) ? g_ecnt[i] : 0;
    s[t] = v;
    __syncthreads();
    for (int d = 1; d < SCAN_B; d <<= 1) {
        int add = (t >= d) ? s[t - d] : 0;
        __syncthreads();
        s[t] += add;
        __syncthreads();
    }
    if (i < N_NODES) {
        int off = g_bpre[blockIdx.x] + s[t] - v;
        g_off[i] = off;
        g_cur[i] = off;
        g_dinv[i] = rsqrtf((float)(v + 1));
    }
}

// ---------------- CSR fill: {src, norm} ------------------------------------
__global__ void k_fill(const void* __restrict__ ei) {
    int e = blockIdx.x * blockDim.x + threadIdx.x;
    int s, d;
    if (g_is32) {
        const int* p = (const int*)ei;
        s = p[e]; d = p[N_EDGES + e];
    } else {
        const long long* p = (const long long*)ei;
        s = (int)p[e]; d = (int)p[N_EDGES + e];
    }
    float nrm = g_dinv[s] * g_dinv[d];
    int slot = atomicAdd(&g_cur[d], 1);
    g_csr[slot] = make_int2(s, __float_as_int(nrm));
}

// ---------------- layer-1 GEMM: h1 = x @ W1 --------------------------------
// 256 rows x 32 cols per block; 8x4 register tile; all-float4 smem traffic.
// Thread rows = i*32 + rowg -> the 4 distinct LDS.128 addresses per warp hit
// banks {0,20,8,28}: conflict-free.
__global__ void __launch_bounds__(256, 2)
k_gemm1(const float* __restrict__ x, const float* __restrict__ W1) {
    __shared__ float4 sX[GB_ROWS * (GKT / 4)];   // [row][5]
    __shared__ float4 sW[GKT * (HID / 4)];       // [k][8]

    const int tid  = threadIdx.x;
    const int row0 = blockIdx.x * GB_ROWS;
    const int colg = tid & 7;
    const int rowg = tid >> 3;

    float4 acc[8];
    #pragma unroll
    for (int i = 0; i < 8; i++) acc[i] = make_float4(0.f, 0.f, 0.f, 0.f);

    for (int kt = 0; kt < F_IN / GKT; kt++) {     // 15 tiles
        const int k0 = kt * GKT;
        // W tile: 20*32 floats = 160 float4, contiguous
        for (int i = tid; i < GKT * 8; i += 256)
            sW[i] = *reinterpret_cast<const float4*>(&W1[k0 * HID + i * 4]);
        // X tile: 256 rows x 5 float4
        for (int i = tid; i < GB_ROWS * 5; i += 256) {
            int r = i / 5, c = i - r * 5;
            int row = row0 + r;
            sX[r * 5 + c] = (row < N_NODES)
                ? *reinterpret_cast<const float4*>(&x[(size_t)row * F_IN + k0 + c * 4])
                : make_float4(0.f, 0.f, 0.f, 0.f);
        }
        __syncthreads();

        #pragma unroll
        for (int kk = 0; kk < 5; kk++) {
            float4 w0 = sW[(kk * 4 + 0) * 8 + colg];
            float4 w1 = sW[(kk * 4 + 1) * 8 + colg];
            float4 w2 = sW[(kk * 4 + 2) * 8 + colg];
            float4 w3 = sW[(kk * 4 + 3) * 8 + colg];
            #pragma unroll
            for (int i = 0; i < 8; i++) {
                float4 xv = sX[(i * 32 + rowg) * 5 + kk];
                acc[i].x += xv.x * w0.x + xv.y * w1.x + xv.z * w2.x + xv.w * w3.x;
                acc[i].y += xv.x * w0.y + xv.y * w1.y + xv.z * w2.y + xv.w * w3.y;
                acc[i].z += xv.x * w0.z + xv.y * w1.z + xv.z * w2.z + xv.w * w3.z;
                acc[i].w += xv.x * w0.w + xv.y * w1.w + xv.z * w2.w + xv.w * w3.w;
            }
        }
        __syncthreads();
    }

    #pragma unroll
    for (int i = 0; i < 8; i++) {
        int row = row0 + i * 32 + rowg;
        if (row < N_NODES) g_h1[row * 8 + colg] = acc[i];
    }
}

// ---------------- fused layer-1 agg + tanh + W2 GEMM -----------------------
// warp per node; lane = nb*8 + sub (nb: neighbor group of 4, sub: float4 col)
__global__ void k_agg1mid(const float* __restrict__ b1, const float* __restrict__ W2) {
    __shared__ float sW2[HID * NCLS];
    __shared__ float sb1[HID];
    int tid = threadIdx.x;
    for (int i = tid; i < HID * NCLS; i += 256) sW2[i] = W2[i];
    if (tid < HID) sb1[tid] = b1[tid];
    __syncthreads();

    int w    = (blockIdx.x * blockDim.x + tid) >> 5;
    int lane = tid & 31;
    int sub  = lane & 7;
    int nb   = lane >> 3;

    int   off = g_off[w];
    int   cnt = g_ecnt[w];
    float di  = g_dinv[w];

    float4 acc = make_float4(0.f, 0.f, 0.f, 0.f);
    if (nb == 0) {                       // self-loop: h1[w] * dinv^2
        float4 h = g_h1[w * 8 + sub];
        float di2 = di * di;
        acc = make_float4(h.x * di2, h.y * di2, h.z * di2, h.w * di2);
    }

    for (int i = nb; i < cnt; i += 4) {
        int2  sn  = g_csr[off + i];
        float nrm = __int_as_float(sn.y);
        float4 v  = g_h1[sn.x * 8 + sub];
        acc.x += v.x * nrm; acc.y += v.y * nrm;
        acc.z += v.z * nrm; acc.w += v.w * nrm;
    }

    #pragma unroll
    for (int m = 8; m <= 16; m <<= 1) {
        acc.x += __shfl_xor_sync(0xFFFFFFFFu, acc.x, m);
        acc.y += __shfl_xor_sync(0xFFFFFFFFu, acc.y, m);
        acc.z += __shfl_xor_sync(0xFFFFFFFFu, acc.z, m);
        acc.w += __shfl_xor_sync(0xFFFFFFFFu, acc.w, m);
    }

    float h[4];
    h[0] = tanh_fast(acc.x + sb1[sub * 4 + 0]);
    h[1] = tanh_fast(acc.y + sb1[sub * 4 + 1]);
    h[2] = tanh_fast(acc.z + sb1[sub * 4 + 2]);
    h[3] = tanh_fast(acc.w + sb1[sub * 4 + 3]);

    float p[NCLS];
    #pragma unroll
    for (int c = 0; c < NCLS; c++) {
        p[c] = h[0] * sW2[(sub * 4 + 0) * NCLS + c]
             + h[1] * sW2[(sub * 4 + 1) * NCLS + c]
             + h[2] * sW2[(sub * 4 + 2) * NCLS + c]
             + h[3] * sW2[(sub * 4 + 3) * NCLS + c];
    }
    #pragma unroll
    for (int m = 1; m <= 4; m <<= 1) {
        #pragma unroll
        for (int c = 0; c < NCLS; c++)
            p[c] += __shfl_xor_sync(0xFFFFFFFFu, p[c], m);
    }

    if (lane == 0)
        g_h2[w * 3 + 0] = make_float4(p[0], p[1], p[2], p[3]);
    else if (lane == 1)
        g_h2[w * 3 + 1] = make_float4(p[4], p[5], p[6], p[7]);
    else if (lane == 2)
        g_h2[w * 3 + 2] = make_float4(p[8], p[9], 0.f, 0.f);
}

// ---------------- fused layer-2 agg + bias + log_softmax -------------------
// warp per node; lane = sub*8 + nb (nb: neighbor group of 8, sub: float4 col)
__global__ void k_agg2out(const float* __restrict__ b2, float* __restrict__ out) {
    __shared__ float sb2[NCLS];
    int tid = threadIdx.x;
    if (tid < NCLS) sb2[tid] = b2[tid];
    __syncthreads();

    int w    = (blockIdx.x * blockDim.x + tid) >> 5;
    int lane = tid & 31;
    int nb   = lane & 7;
    int sub  = lane >> 3;
    int csub = (sub < 3) ? sub : 2;

    int   off = g_off[w];
    int   cnt = g_ecnt[w];
    float di  = g_dinv[w];

    float4 acc = make_float4(0.f, 0.f, 0.f, 0.f);
    if (nb == 0 && sub < 3) {            // self-loop
        float4 h = g_h2[w * 3 + sub];
        float di2 = di * di;
        acc = make_float4(h.x * di2, h.y * di2, h.z * di2, h.w * di2);
    }

    for (int i = nb; i < cnt; i += 8) {
        int2  sn  = g_csr[off + i];
        float nrm = __int_as_float(sn.y);
        float4 v  = g_h2[sn.x * 3 + csub];
        acc.x += v.x * nrm; acc.y += v.y * nrm;
        acc.z += v.z * nrm; acc.w += v.w * nrm;
    }

    #pragma unroll
    for (int m = 1; m <= 4; m <<= 1) {
        acc.x += __shfl_xor_sync(0xFFFFFFFFu, acc.x, m);
        acc.y += __shfl_xor_sync(0xFFFFFFFFu, acc.y, m);
        acc.z += __shfl_xor_sync(0xFFFFFFFFu, acc.z, m);
        acc.w += __shfl_xor_sync(0xFFFFFFFFu, acc.w, m);
    }

    float v[NCLS];
    v[0] = __shfl_sync(0xFFFFFFFFu, acc.x, 0)  + sb2[0];
    v[1] = __shfl_sync(0xFFFFFFFFu, acc.y, 0)  + sb2[1];
    v[2] = __shfl_sync(0xFFFFFFFFu, acc.z, 0)  + sb2[2];
    v[3] = __shfl_sync(0xFFFFFFFFu, acc.w, 0)  + sb2[3];
    v[4] = __shfl_sync(0xFFFFFFFFu, acc.x, 8)  + sb2[4];
    v[5] = __shfl_sync(0xFFFFFFFFu, acc.y, 8)  + sb2[5];
    v[6] = __shfl_sync(0xFFFFFFFFu, acc.z, 8)  + sb2[6];
    v[7] = __shfl_sync(0xFFFFFFFFu, acc.w, 8)  + sb2[7];
    v[8] = __shfl_sync(0xFFFFFFFFu, acc.x, 16) + sb2[8];
    v[9] = __shfl_sync(0xFFFFFFFFu, acc.y, 16) + sb2[9];

    float m = v[0];
    #pragma unroll
    for (int c = 1; c < NCLS; c++) m = fmaxf(m, v[c]);
    float s = 0.f;
    #pragma unroll
    for (int c = 0; c < NCLS; c++) s += expf(v[c] - m);
    float ls = logf(s) + m;

    if (lane < NCLS) out[(size_t)w * NCLS + lane] = v[lane] - ls;
}

// ---------------- launch ---------------------------------------------------
extern "C" void kernel_launch(void* const* d_in, const int* in_sizes, int n_in,
                              void* d_out, int out_size) {
    const float* x  = (const float*)d_in[0];
    const void*  ei = d_in[1];
    const float* W1 = (const float*)d_in[2];
    const float* b1 = (const float*)d_in[3];
    const float* W2 = (const float*)d_in[4];
    const float* b2 = (const float*)d_in[5];
    float*       out = (float*)d_out;

    k_detect_zero<<<(N_NODES + 255) / 256, 256>>>((const unsigned long long*)ei); // 0
    k_hist       <<<N_EDGES / 256, 256>>>(ei);                                    // 1
    k_scan_reduce<<<SCAN_NBLK, SCAN_B>>>();                                       // 2
    k_gemm1      <<<(N_NODES + GB_ROWS - 1) / GB_ROWS, 256>>>(x, W1);             // 3 <- profiled
    k_scan_mid   <<<1, 1>>>();                                                    // 4
    k_scan_write <<<SCAN_NBLK, SCAN_B>>>();                                       // 5
    k_fill       <<<N_EDGES / 256, 256>>>(ei);                                    // 6
    k_agg1mid    <<<N_NODES * 32 / 256, 256>>>(b1, W2);                           // 7
    k_agg2out    <<<N_NODES * 32 / 256, 256>>>(b2, out);                          // 8
}

// round 10
// speedup vs baseline: 1.2811x; 1.2811x over previous
#include <cuda_runtime.h>
#include <cstdint>

#define N_NODES 100000
#define N_EDGES 3200000
#define F_IN    300
#define HID     32
#define NCLS    10

#define SCAN_B  512
#define SCAN_NBLK ((N_NODES + SCAN_B - 1) / SCAN_B)   // 196

#define GT_ROWS 128          // gemm1 rows per block
#define GKT     40           // gemm1 k-tile (5 mma k-steps)
#define SXS     44           // sX row stride in floats (11 float4) - conflict-free
#define SWS     44           // sWt row stride in floats (>= GKT, padded)

// ---------------- scratch (device globals: no allocation allowed) ----------
__device__ int    g_is32;
__device__ int    g_ecnt[N_NODES];
__device__ int    g_off [N_NODES];
__device__ int    g_cur [N_NODES];
__device__ int    g_bsum[SCAN_NBLK];
__device__ int    g_bpre[SCAN_NBLK];
__device__ float  g_dinv[N_NODES];
__device__ int2   g_csr [N_EDGES];               // {src, norm-as-int} 25.6 MB
__device__ float4 g_h1  [N_NODES * (HID / 4)];   // 12.8 MB
__device__ float4 g_h2  [N_NODES * 3];           // 4.8 MB (10 -> 12 padded)

__device__ __forceinline__ float tanh_fast(float x) {
    float y;
    asm("tanh.approx.f32 %0, %1;" : "=f"(y) : "f"(x));
    return y;
}

__device__ __forceinline__ unsigned tf32_of(float v) {
    unsigned t;
    asm("cvt.rna.tf32.f32 %0, %1;" : "=r"(t) : "f"(v));
    return t;
}

// ---------------- detect dtype + zero histogram (fused) --------------------
__global__ void k_detect_zero(const unsigned long long* __restrict__ ei) {
    int i = blockIdx.x * blockDim.x + threadIdx.x;
    if (i < N_NODES) g_ecnt[i] = 0;
    if (blockIdx.x == 0) {
        unsigned long long v = ei[threadIdx.x];
        int any = __syncthreads_or(v > 0xFFFFFFFFull ? 1 : 0);
        if (threadIdx.x == 0) g_is32 = any;
    }
}

__global__ void k_hist(const void* __restrict__ ei) {
    int e = blockIdx.x * blockDim.x + threadIdx.x;
    int d = g_is32 ? ((const int*)ei)[N_EDGES + e]
                   : (int)((const long long*)ei)[N_EDGES + e];
    atomicAdd(&g_ecnt[d], 1);
}

// ---------------- 3-kernel exclusive scan ----------------------------------
__global__ void k_scan_reduce() {
    __shared__ int s[SCAN_B];
    int i = blockIdx.x * SCAN_B + threadIdx.x;
    s[threadIdx.x] = (i < N_NODES) ? g_ecnt[i] : 0;
    __syncthreads();
    for (int d = SCAN_B / 2; d > 0; d >>= 1) {
        if (threadIdx.x < d) s[threadIdx.x] += s[threadIdx.x + d];
        __syncthreads();
    }
    if (threadIdx.x == 0) g_bsum[blockIdx.x] = s[0];
}

__global__ void k_scan_mid() {
    int run = 0;
    for (int b = 0; b < SCAN_NBLK; b++) { g_bpre[b] = run; run += g_bsum[b]; }
}

__global__ void k_scan_write() {
    __shared__ int s[SCAN_B];
    int t = threadIdx.x;
    int i = blockIdx.x * SCAN_B + t;
    int v = (i < N_NODES) ? g_ecnt[i] : 0;
    s[t] = v;
    __syncthreads();
    for (int d = 1; d < SCAN_B; d <<= 1) {
        int add = (t >= d) ? s[t - d] : 0;
        __syncthreads();
        s[t] += add;
        __syncthreads();
    }
    if (i < N_NODES) {
        int off = g_bpre[blockIdx.x] + s[t] - v;
        g_off[i] = off;
        g_cur[i] = off;
        g_dinv[i] = rsqrtf((float)(v + 1));
    }
}

// ---------------- CSR fill: {src, norm} ------------------------------------
__global__ void k_fill(const void* __restrict__ ei) {
    int e = blockIdx.x * blockDim.x + threadIdx.x;
    int s, d;
    if (g_is32) {
        const int* p = (const int*)ei;
        s = p[e]; d = p[N_EDGES + e];
    } else {
        const long long* p = (const long long*)ei;
        s = (int)p[e]; d = (int)p[N_EDGES + e];
    }
    float nrm = g_dinv[s] * g_dinv[d];
    int slot = atomicAdd(&g_cur[d], 1);
    g_csr[slot] = make_int2(s, __float_as_int(nrm));
}

// ---------------- layer-1 GEMM via tf32 tensor cores -----------------------
// 128 rows x 32 cols per block, 8 warps; warp w owns rows w*16..w*16+15,
// computing 4 m16n8k8 tiles across the 32 columns. K tiled by 40.
__global__ void __launch_bounds__(256)
k_gemm1(const float* __restrict__ x, const float* __restrict__ W1) {
    __shared__ uint4    sX4[GT_ROWS * (SXS / 4)];   // tf32 bits, row stride 11 uint4
    __shared__ unsigned sWt[HID * SWS];             // W transposed [n][k]

    const int tid  = threadIdx.x;
    const int w    = tid >> 5;
    const int lane = tid & 31;
    const int g    = lane >> 2;     // 0..7
    const int c    = lane & 3;      // 0..3
    const int row0 = blockIdx.x * GT_ROWS;
    const int wrow = w * 16;

    const unsigned* sxu = reinterpret_cast<const unsigned*>(sX4);

    float acc[4][4];                // [n-tile][c0..c3]
    #pragma unroll
    for (int nt = 0; nt < 4; nt++)
        #pragma unroll
        for (int j = 0; j < 4; j++) acc[nt][j] = 0.f;

    for (int kt = 0; kt < 8; kt++) {                 // ceil(300/40)=8, last padded
        const int k0 = kt * GKT;

        // W tile, transposed + tf32: sWt[n][k]
        for (int i = tid; i < GKT * HID; i += 256) {
            int k = i >> 5, n = i & 31;
            float v = (k0 + k < F_IN) ? W1[(k0 + k) * HID + n] : 0.f;
            sWt[n * SWS + k] = tf32_of(v);
        }
        // X tile, tf32: rows 0..127, 10 float4 each, stored at stride 11
        for (int i = tid; i < GT_ROWS * (GKT / 4); i += 256) {
            int r = i / (GKT / 4), cc = i % (GKT / 4);
            int row = row0 + r, col = k0 + cc * 4;
            uint4 t = make_uint4(0u, 0u, 0u, 0u);
            if (row < N_NODES && col < F_IN) {
                float4 v = *reinterpret_cast<const float4*>(&x[(size_t)row * F_IN + col]);
                t.x = tf32_of(v.x); t.y = tf32_of(v.y);
                t.z = tf32_of(v.z); t.w = tf32_of(v.w);
            }
            sX4[r * (SXS / 4) + cc] = t;
        }
        __syncthreads();

        #pragma unroll
        for (int ks = 0; ks < 5; ks++) {
            const int k = ks * 8;
            unsigned a0 = sxu[(wrow + g)     * SXS + k + c];
            unsigned a1 = sxu[(wrow + g + 8) * SXS + k + c];
            unsigned a2 = sxu[(wrow + g)     * SXS + k + c + 4];
            unsigned a3 = sxu[(wrow + g + 8) * SXS + k + c + 4];
            #pragma unroll
            for (int nt = 0; nt < 4; nt++) {
                unsigned b0 = sWt[(nt * 8 + g) * SWS + k + c];
                unsigned b1 = sWt[(nt * 8 + g) * SWS + k + c + 4];
                asm volatile(
                    "mma.sync.aligned.m16n8k8.row.col.f32.tf32.tf32.f32 "
                    "{%0,%1,%2,%3}, {%4,%5,%6,%7}, {%8,%9}, {%0,%1,%2,%3};"
                    : "+f"(acc[nt][0]), "+f"(acc[nt][1]),
                      "+f"(acc[nt][2]), "+f"(acc[nt][3])
                    : "r"(a0), "r"(a1), "r"(a2), "r"(a3), "r"(b0), "r"(b1));
            }
        }
        __syncthreads();
    }

    // epilogue: c0,c1 -> (row wrow+g, col nt*8 + c*2); c2,c3 -> row +8
    float* h1f = reinterpret_cast<float*>(g_h1);
    int r0i = row0 + wrow + g;
    int r1i = r0i + 8;
    #pragma unroll
    for (int nt = 0; nt < 4; nt++) {
        int col = nt * 8 + c * 2;
        if (r0i < N_NODES)
            *reinterpret_cast<float2*>(&h1f[(size_t)r0i * HID + col]) =
                make_float2(acc[nt][0], acc[nt][1]);
        if (r1i < N_NODES)
            *reinterpret_cast<float2*>(&h1f[(size_t)r1i * HID + col]) =
                make_float2(acc[nt][2], acc[nt][3]);
    }
}

// ---------------- fused layer-1 agg + tanh + W2 GEMM -----------------------
// warp per node; lane = nb*8 + sub (nb: neighbor group of 4, sub: float4 col)
__global__ void k_agg1mid(const float* __restrict__ b1, const float* __restrict__ W2) {
    __shared__ float sW2[HID * NCLS];
    __shared__ float sb1[HID];
    int tid = threadIdx.x;
    for (int i = tid; i < HID * NCLS; i += 256) sW2[i] = W2[i];
    if (tid < HID) sb1[tid] = b1[tid];
    __syncthreads();

    int w    = (blockIdx.x * blockDim.x + tid) >> 5;
    int lane = tid & 31;
    int sub  = lane & 7;
    int nb   = lane >> 3;

    int   off = g_off[w];
    int   cnt = g_ecnt[w];
    float di  = g_dinv[w];

    float4 acc = make_float4(0.f, 0.f, 0.f, 0.f);
    if (nb == 0) {                       // self-loop: h1[w] * dinv^2
        float4 h = g_h1[w * 8 + sub];
        float di2 = di * di;
        acc = make_float4(h.x * di2, h.y * di2, h.z * di2, h.w * di2);
    }

    for (int i = nb; i < cnt; i += 4) {
        int2  sn  = g_csr[off + i];
        float nrm = __int_as_float(sn.y);
        float4 v  = g_h1[sn.x * 8 + sub];
        acc.x += v.x * nrm; acc.y += v.y * nrm;
        acc.z += v.z * nrm; acc.w += v.w * nrm;
    }

    #pragma unroll
    for (int m = 8; m <= 16; m <<= 1) {
        acc.x += __shfl_xor_sync(0xFFFFFFFFu, acc.x, m);
        acc.y += __shfl_xor_sync(0xFFFFFFFFu, acc.y, m);
        acc.z += __shfl_xor_sync(0xFFFFFFFFu, acc.z, m);
        acc.w += __shfl_xor_sync(0xFFFFFFFFu, acc.w, m);
    }

    float h[4];
    h[0] = tanh_fast(acc.x + sb1[sub * 4 + 0]);
    h[1] = tanh_fast(acc.y + sb1[sub * 4 + 1]);
    h[2] = tanh_fast(acc.z + sb1[sub * 4 + 2]);
    h[3] = tanh_fast(acc.w + sb1[sub * 4 + 3]);

    float p[NCLS];
    #pragma unroll
    for (int c = 0; c < NCLS; c++) {
        p[c] = h[0] * sW2[(sub * 4 + 0) * NCLS + c]
             + h[1] * sW2[(sub * 4 + 1) * NCLS + c]
             + h[2] * sW2[(sub * 4 + 2) * NCLS + c]
             + h[3] * sW2[(sub * 4 + 3) * NCLS + c];
    }
    #pragma unroll
    for (int m = 1; m <= 4; m <<= 1) {
        #pragma unroll
        for (int c = 0; c < NCLS; c++)
            p[c] += __shfl_xor_sync(0xFFFFFFFFu, p[c], m);
    }

    if (lane == 0)
        g_h2[w * 3 + 0] = make_float4(p[0], p[1], p[2], p[3]);
    else if (lane == 1)
        g_h2[w * 3 + 1] = make_float4(p[4], p[5], p[6], p[7]);
    else if (lane == 2)
        g_h2[w * 3 + 2] = make_float4(p[8], p[9], 0.f, 0.f);
}

// ---------------- fused layer-2 agg + bias + log_softmax -------------------
// warp per node; lane = sub*8 + nb (nb: neighbor group of 8, sub: float4 col)
__global__ void k_agg2out(const float* __restrict__ b2, float* __restrict__ out) {
    __shared__ float sb2[NCLS];
    int tid = threadIdx.x;
    if (tid < NCLS) sb2[tid] = b2[tid];
    __syncthreads();

    int w    = (blockIdx.x * blockDim.x + tid) >> 5;
    int lane = tid & 31;
    int nb   = lane & 7;
    int sub  = lane >> 3;
    int csub = (sub < 3) ? sub : 2;

    int   off = g_off[w];
    int   cnt = g_ecnt[w];
    float di  = g_dinv[w];

    float4 acc = make_float4(0.f, 0.f, 0.f, 0.f);
    if (nb == 0 && sub < 3) {            // self-loop
        float4 h = g_h2[w * 3 + sub];
        float di2 = di * di;
        acc = make_float4(h.x * di2, h.y * di2, h.z * di2, h.w * di2);
    }

    for (int i = nb; i < cnt; i += 8) {
        int2  sn  = g_csr[off + i];
        float nrm = __int_as_float(sn.y);
        float4 v  = g_h2[sn.x * 3 + csub];
        acc.x += v.x * nrm; acc.y += v.y * nrm;
        acc.z += v.z * nrm; acc.w += v.w * nrm;
    }

    #pragma unroll
    for (int m = 1; m <= 4; m <<= 1) {
        acc.x += __shfl_xor_sync(0xFFFFFFFFu, acc.x, m);
        acc.y += __shfl_xor_sync(0xFFFFFFFFu, acc.y, m);
        acc.z += __shfl_xor_sync(0xFFFFFFFFu, acc.z, m);
        acc.w += __shfl_xor_sync(0xFFFFFFFFu, acc.w, m);
    }

    float v[NCLS];
    v[0] = __shfl_sync(0xFFFFFFFFu, acc.x, 0)  + sb2[0];
    v[1] = __shfl_sync(0xFFFFFFFFu, acc.y, 0)  + sb2[1];
    v[2] = __shfl_sync(0xFFFFFFFFu, acc.z, 0)  + sb2[2];
    v[3] = __shfl_sync(0xFFFFFFFFu, acc.w, 0)  + sb2[3];
    v[4] = __shfl_sync(0xFFFFFFFFu, acc.x, 8)  + sb2[4];
    v[5] = __shfl_sync(0xFFFFFFFFu, acc.y, 8)  + sb2[5];
    v[6] = __shfl_sync(0xFFFFFFFFu, acc.z, 8)  + sb2[6];
    v[7] = __shfl_sync(0xFFFFFFFFu, acc.w, 8)  + sb2[7];
    v[8] = __shfl_sync(0xFFFFFFFFu, acc.x, 16) + sb2[8];
    v[9] = __shfl_sync(0xFFFFFFFFu, acc.y, 16) + sb2[9];

    float m = v[0];
    #pragma unroll
    for (int c = 1; c < NCLS; c++) m = fmaxf(m, v[c]);
    float s = 0.f;
    #pragma unroll
    for (int c = 0; c < NCLS; c++) s += expf(v[c] - m);
    float ls = logf(s) + m;

    if (lane < NCLS) out[(size_t)w * NCLS + lane] = v[lane] - ls;
}

// ---------------- launch ---------------------------------------------------
extern "C" void kernel_launch(void* const* d_in, const int* in_sizes, int n_in,
                              void* d_out, int out_size) {
    const float* x  = (const float*)d_in[0];
    const void*  ei = d_in[1];
    const float* W1 = (const float*)d_in[2];
    const float* b1 = (const float*)d_in[3];
    const float* W2 = (const float*)d_in[4];
    const float* b2 = (const float*)d_in[5];
    float*       out = (float*)d_out;

    k_detect_zero<<<(N_NODES + 255) / 256, 256>>>((const unsigned long long*)ei); // 0
    k_hist       <<<N_EDGES / 256, 256>>>(ei);                                    // 1
    k_scan_reduce<<<SCAN_NBLK, SCAN_B>>>();                                       // 2
    k_gemm1      <<<(N_NODES + GT_ROWS - 1) / GT_ROWS, 256>>>(x, W1);             // 3 <- profiled
    k_scan_mid   <<<1, 1>>>();                                                    // 4
    k_scan_write <<<SCAN_NBLK, SCAN_B>>>();                                       // 5
    k_fill       <<<N_EDGES / 256, 256>>>(ei);                                    // 6
    k_agg1mid    <<<N_NODES * 32 / 256, 256>>>(b1, W2);                           // 7
    k_agg2out    <<<N_NODES * 32 / 256, 256>>>(b2, out);                          // 8
}

// round 11
// speedup vs baseline: 1.3881x; 1.0835x over previous
#include <cuda_runtime.h>
#include <cuda_fp16.h>
#include <cstdint>

#define N_NODES 100000
#define N_EDGES 3200000
#define F_IN    300
#define HID     32
#define NCLS    10

#define SCAN_B  512
#define SCAN_NBLK ((N_NODES + SCAN_B - 1) / SCAN_B)   // 196

#define GT_ROWS 128          // gemm1 rows per block
#define GKT     40           // gemm1 k-tile (5 mma k-steps)
#define SXS     44           // sX row stride in floats - conflict-free
#define SWS     44           // sWt row stride in floats (>= GKT, padded)

// ---------------- scratch (device globals: no allocation allowed) ----------
__device__ int    g_is32;
__device__ int    g_ecnt[N_NODES];
__device__ int    g_off [N_NODES];
__device__ int    g_cur [N_NODES];
__device__ int    g_bsum[SCAN_NBLK];
__device__ int    g_bpre[SCAN_NBLK];
__device__ float  g_dinv[N_NODES];
__device__ int    g_csr [N_EDGES];           // src only, 12.8 MB
__device__ uint4  g_h1h [N_NODES * 4];       // h1*dinv as fp16, 64B/row, 6.4 MB
__device__ uint2  g_h2h [N_NODES * 3];       // h2*dinv as fp16, 24B/row, 2.4 MB

__device__ __forceinline__ float tanh_fast(float x) {
    float y;
    asm("tanh.approx.f32 %0, %1;" : "=f"(y) : "f"(x));
    return y;
}

__device__ __forceinline__ unsigned tf32_of(float v) {
    unsigned t;
    asm("cvt.rna.tf32.f32 %0, %1;" : "=r"(t) : "f"(v));
    return t;
}

// ---------------- detect dtype + zero histogram (fused) --------------------
__global__ void k_detect_zero(const unsigned long long* __restrict__ ei) {
    int i = blockIdx.x * blockDim.x + threadIdx.x;
    if (i < N_NODES) g_ecnt[i] = 0;
    if (blockIdx.x == 0) {
        unsigned long long v = ei[threadIdx.x];
        int any = __syncthreads_or(v > 0xFFFFFFFFull ? 1 : 0);
        if (threadIdx.x == 0) g_is32 = any;
    }
}

__global__ void k_hist(const void* __restrict__ ei) {
    int e = blockIdx.x * blockDim.x + threadIdx.x;
    int d = g_is32 ? ((const int*)ei)[N_EDGES + e]
                   : (int)((const long long*)ei)[N_EDGES + e];
    atomicAdd(&g_ecnt[d], 1);
}

__global__ void k_dinv() {
    int i = blockIdx.x * blockDim.x + threadIdx.x;
    if (i < N_NODES) g_dinv[i] = rsqrtf((float)(g_ecnt[i] + 1));
}

// ---------------- layer-1 GEMM via tf32 tensor cores -----------------------
// Output: g_h1h[row] = (x @ W1)[row] * dinv[row], fp16.
__global__ void __launch_bounds__(256)
k_gemm1(const float* __restrict__ x, const float* __restrict__ W1) {
    __shared__ uint4    sX4[GT_ROWS * (SXS / 4)];
    __shared__ unsigned sWt[HID * SWS];

    const int tid  = threadIdx.x;
    const int w    = tid >> 5;
    const int lane = tid & 31;
    const int g    = lane >> 2;     // 0..7
    const int c    = lane & 3;      // 0..3
    const int row0 = blockIdx.x * GT_ROWS;
    const int wrow = w * 16;

    const unsigned* sxu = reinterpret_cast<const unsigned*>(sX4);

    float acc[4][4];
    #pragma unroll
    for (int nt = 0; nt < 4; nt++)
        #pragma unroll
        for (int j = 0; j < 4; j++) acc[nt][j] = 0.f;

    for (int kt = 0; kt < 8; kt++) {
        const int k0 = kt * GKT;

        for (int i = tid; i < GKT * HID; i += 256) {
            int k = i >> 5, n = i & 31;
            float v = (k0 + k < F_IN) ? W1[(k0 + k) * HID + n] : 0.f;
            sWt[n * SWS + k] = tf32_of(v);
        }
        for (int i = tid; i < GT_ROWS * (GKT / 4); i += 256) {
            int r = i / (GKT / 4), cc = i % (GKT / 4);
            int row = row0 + r, col = k0 + cc * 4;
            uint4 t = make_uint4(0u, 0u, 0u, 0u);
            if (row < N_NODES && col < F_IN) {
                float4 v = *reinterpret_cast<const float4*>(&x[(size_t)row * F_IN + col]);
                t.x = tf32_of(v.x); t.y = tf32_of(v.y);
                t.z = tf32_of(v.z); t.w = tf32_of(v.w);
            }
            sX4[r * (SXS / 4) + cc] = t;
        }
        __syncthreads();

        #pragma unroll
        for (int ks = 0; ks < 5; ks++) {
            const int k = ks * 8;
            unsigned a0 = sxu[(wrow + g)     * SXS + k + c];
            unsigned a1 = sxu[(wrow + g + 8) * SXS + k + c];
            unsigned a2 = sxu[(wrow + g)     * SXS + k + c + 4];
            unsigned a3 = sxu[(wrow + g + 8) * SXS + k + c + 4];
            #pragma unroll
            for (int nt = 0; nt < 4; nt++) {
                unsigned b0 = sWt[(nt * 8 + g) * SWS + k + c];
                unsigned b1 = sWt[(nt * 8 + g) * SWS + k + c + 4];
                asm volatile(
                    "mma.sync.aligned.m16n8k8.row.col.f32.tf32.tf32.f32 "
                    "{%0,%1,%2,%3}, {%4,%5,%6,%7}, {%8,%9}, {%0,%1,%2,%3};"
                    : "+f"(acc[nt][0]), "+f"(acc[nt][1]),
                      "+f"(acc[nt][2]), "+f"(acc[nt][3])
                    : "r"(a0), "r"(a1), "r"(a2), "r"(a3), "r"(b0), "r"(b1));
            }
        }
        __syncthreads();
    }

    // epilogue: scale by dinv, write fp16
    __half* h1h = reinterpret_cast<__half*>(g_h1h);
    int r0i = row0 + wrow + g;
    int r1i = r0i + 8;
    float d0 = (r0i < N_NODES) ? g_dinv[r0i] : 0.f;
    float d1 = (r1i < N_NODES) ? g_dinv[r1i] : 0.f;
    #pragma unroll
    for (int nt = 0; nt < 4; nt++) {
        int col = nt * 8 + c * 2;
        if (r0i < N_NODES)
            *reinterpret_cast<__half2*>(&h1h[(size_t)r0i * HID + col]) =
                __floats2half2_rn(acc[nt][0] * d0, acc[nt][1] * d0);
        if (r1i < N_NODES)
            *reinterpret_cast<__half2*>(&h1h[(size_t)r1i * HID + col]) =
                __floats2half2_rn(acc[nt][2] * d1, acc[nt][3] * d1);
    }
}

// ---------------- 3-kernel exclusive scan ----------------------------------
__global__ void k_scan_reduce() {
    __shared__ int s[SCAN_B];
    int i = blockIdx.x * SCAN_B + threadIdx.x;
    s[threadIdx.x] = (i < N_NODES) ? g_ecnt[i] : 0;
    __syncthreads();
    for (int d = SCAN_B / 2; d > 0; d >>= 1) {
        if (threadIdx.x < d) s[threadIdx.x] += s[threadIdx.x + d];
        __syncthreads();
    }
    if (threadIdx.x == 0) g_bsum[blockIdx.x] = s[0];
}

__global__ void k_scan_mid() {
    int run = 0;
    for (int b = 0; b < SCAN_NBLK; b++) { g_bpre[b] = run; run += g_bsum[b]; }
}

__global__ void k_scan_write() {
    __shared__ int s[SCAN_B];
    int t = threadIdx.x;
    int i = blockIdx.x * SCAN_B + t;
    int v = (i < N_NODES) ? g_ecnt[i] : 0;
    s[t] = v;
    __syncthreads();
    for (int d = 1; d < SCAN_B; d <<= 1) {
        int add = (t >= d) ? s[t - d] : 0;
        __syncthreads();
        s[t] += add;
        __syncthreads();
    }
    if (i < N_NODES) {
        int off = g_bpre[blockIdx.x] + s[t] - v;
        g_off[i] = off;
        g_cur[i] = off;
    }
}

// ---------------- CSR fill: src only ---------------------------------------
__global__ void k_fill(const void* __restrict__ ei) {
    int e = blockIdx.x * blockDim.x + threadIdx.x;
    int s, d;
    if (g_is32) {
        const int* p = (const int*)ei;
        s = p[e]; d = p[N_EDGES + e];
    } else {
        const long long* p = (const long long*)ei;
        s = (int)p[e]; d = (int)p[N_EDGES + e];
    }
    int slot = atomicAdd(&g_cur[d], 1);
    g_csr[slot] = s;
}

// ---------------- fused layer-1 agg + tanh + W2 GEMM -----------------------
// warp per node; lane: sub = lane&3 (uint4 chunk of 8 feats), nb = lane>>2
// agg = dinv[w] * (sum_e h1s[src] + h1s[w]);  h1s already scaled by dinv[src].
__global__ void k_agg1mid(const float* __restrict__ b1, const float* __restrict__ W2) {
    __shared__ float sW2[HID * NCLS];
    __shared__ float sb1[HID];
    int tid = threadIdx.x;
    for (int i = tid; i < HID * NCLS; i += 256) sW2[i] = W2[i];
    if (tid < HID) sb1[tid] = b1[tid];
    __syncthreads();

    int w    = (blockIdx.x * blockDim.x + tid) >> 5;
    int lane = tid & 31;
    int sub  = lane & 3;
    int nb   = lane >> 2;          // 0..7

    int   off = g_off[w];
    int   cnt = g_ecnt[w];
    float di  = g_dinv[w];

    float acc[8];
    #pragma unroll
    for (int j = 0; j < 8; j++) acc[j] = 0.f;

    if (nb == 0) {                 // self-loop term (already dinv-scaled)
        uint4 u = g_h1h[w * 4 + sub];
        const __half2* hp = reinterpret_cast<const __half2*>(&u);
        #pragma unroll
        for (int j = 0; j < 4; j++) {
            float2 f = __half22float2(hp[j]);
            acc[2 * j] += f.x; acc[2 * j + 1] += f.y;
        }
    }

    for (int i = nb; i < cnt; i += 8) {
        int   src = g_csr[off + i];
        uint4 u = g_h1h[src * 4 + sub];
        const __half2* hp = reinterpret_cast<const __half2*>(&u);
        #pragma unroll
        for (int j = 0; j < 4; j++) {
            float2 f = __half22float2(hp[j]);
            acc[2 * j] += f.x; acc[2 * j + 1] += f.y;
        }
    }

    // reduce over nb (lane bits 2..4)
    #pragma unroll
    for (int m = 4; m <= 16; m <<= 1)
        #pragma unroll
        for (int j = 0; j < 8; j++)
            acc[j] += __shfl_xor_sync(0xFFFFFFFFu, acc[j], m);

    // this lane now owns 8 features (sub*8 + j) of agg = di * sum
    float h[8];
    #pragma unroll
    for (int j = 0; j < 8; j++)
        h[j] = tanh_fast(di * acc[j] + sb1[sub * 8 + j]);

    float p[NCLS];
    #pragma unroll
    for (int c = 0; c < NCLS; c++) {
        float s = 0.f;
        #pragma unroll
        for (int j = 0; j < 8; j++)
            s += h[j] * sW2[(sub * 8 + j) * NCLS + c];
        p[c] = s;
    }
    // reduce over sub (lane bits 0..1)
    #pragma unroll
    for (int m = 1; m <= 2; m <<= 1)
        #pragma unroll
        for (int c = 0; c < NCLS; c++)
            p[c] += __shfl_xor_sync(0xFFFFFFFFu, p[c], m);

    // h2s = p * dinv[w], fp16 (12 halfs: 10 + 2 pad)
    if (lane == 0) {
        __half2 a = __floats2half2_rn(p[0] * di, p[1] * di);
        __half2 b = __floats2half2_rn(p[2] * di, p[3] * di);
        g_h2h[w * 3 + 0] = make_uint2(*(unsigned*)&a, *(unsigned*)&b);
    } else if (lane == 1) {
        __half2 a = __floats2half2_rn(p[4] * di, p[5] * di);
        __half2 b = __floats2half2_rn(p[6] * di, p[7] * di);
        g_h2h[w * 3 + 1] = make_uint2(*(unsigned*)&a, *(unsigned*)&b);
    } else if (lane == 2) {
        __half2 a = __floats2half2_rn(p[8] * di, p[9] * di);
        __half2 b = __floats2half2_rn(0.f, 0.f);
        g_h2h[w * 3 + 2] = make_uint2(*(unsigned*)&a, *(unsigned*)&b);
    }
}

// ---------------- fused layer-2 agg + bias + log_softmax -------------------
// warp per node; lane: nb = lane&7, sub = lane>>3 (uint2 chunk of 4 feats)
__global__ void k_agg2out(const float* __restrict__ b2, float* __restrict__ out) {
    __shared__ float sb2[NCLS];
    int tid = threadIdx.x;
    if (tid < NCLS) sb2[tid] = b2[tid];
    __syncthreads();

    int w    = (blockIdx.x * blockDim.x + tid) >> 5;
    int lane = tid & 31;
    int nb   = lane & 7;
    int sub  = lane >> 3;          // 0..3
    int csub = (sub < 3) ? sub : 2;

    int   off = g_off[w];
    int   cnt = g_ecnt[w];
    float di  = g_dinv[w];

    float acc[4];
    #pragma unroll
    for (int j = 0; j < 4; j++) acc[j] = 0.f;

    if (nb == 0 && sub < 3) {      // self-loop
        uint2 u = g_h2h[w * 3 + sub];
        float2 f0 = __half22float2(*(const __half2*)&u.x);
        float2 f1 = __half22float2(*(const __half2*)&u.y);
        acc[0] += f0.x; acc[1] += f0.y; acc[2] += f1.x; acc[3] += f1.y;
    }

    for (int i = nb; i < cnt; i += 8) {
        int   src = g_csr[off + i];
        uint2 u = g_h2h[src * 3 + csub];
        float2 f0 = __half22float2(*(const __half2*)&u.x);
        float2 f1 = __half22float2(*(const __half2*)&u.y);
        acc[0] += f0.x; acc[1] += f0.y; acc[2] += f1.x; acc[3] += f1.y;
    }

    // reduce over nb (lane bits 0..2)
    #pragma unroll
    for (int m = 1; m <= 4; m <<= 1)
        #pragma unroll
        for (int j = 0; j < 4; j++)
            acc[j] += __shfl_xor_sync(0xFFFFFFFFu, acc[j], m);

    float v[NCLS];
    v[0] = di * __shfl_sync(0xFFFFFFFFu, acc[0], 0)  + sb2[0];
    v[1] = di * __shfl_sync(0xFFFFFFFFu, acc[1], 0)  + sb2[1];
    v[2] = di * __shfl_sync(0xFFFFFFFFu, acc[2], 0)  + sb2[2];
    v[3] = di * __shfl_sync(0xFFFFFFFFu, acc[3], 0)  + sb2[3];
    v[4] = di * __shfl_sync(0xFFFFFFFFu, acc[0], 8)  + sb2[4];
    v[5] = di * __shfl_sync(0xFFFFFFFFu, acc[1], 8)  + sb2[5];
    v[6] = di * __shfl_sync(0xFFFFFFFFu, acc[2], 8)  + sb2[6];
    v[7] = di * __shfl_sync(0xFFFFFFFFu, acc[3], 8)  + sb2[7];
    v[8] = di * __shfl_sync(0xFFFFFFFFu, acc[0], 16) + sb2[8];
    v[9] = di * __shfl_sync(0xFFFFFFFFu, acc[1], 16) + sb2[9];

    float m = v[0];
    #pragma unroll
    for (int c = 1; c < NCLS; c++) m = fmaxf(m, v[c]);
    float s = 0.f;
    #pragma unroll
    for (int c = 0; c < NCLS; c++) s += expf(v[c] - m);
    float ls = logf(s) + m;

    if (lane < NCLS) out[(size_t)w * NCLS + lane] = v[lane] - ls;
}

// ---------------- launch ---------------------------------------------------
extern "C" void kernel_launch(void* const* d_in, const int* in_sizes, int n_in,
                              void* d_out, int out_size) {
    const float* x  = (const float*)d_in[0];
    const void*  ei = d_in[1];
    const float* W1 = (const float*)d_in[2];
    const float* b1 = (const float*)d_in[3];
    const float* W2 = (const float*)d_in[4];
    const float* b2 = (const float*)d_in[5];
    float*       out = (float*)d_out;

    k_detect_zero<<<(N_NODES + 255) / 256, 256>>>((const unsigned long long*)ei); // 0
    k_hist       <<<N_EDGES / 256, 256>>>(ei);                                    // 1
    k_dinv       <<<(N_NODES + 255) / 256, 256>>>();                              // 2
    k_gemm1      <<<(N_NODES + GT_ROWS - 1) / GT_ROWS, 256>>>(x, W1);             // 3 <- profiled
    k_scan_reduce<<<SCAN_NBLK, SCAN_B>>>();                                       // 4
    k_scan_mid   <<<1, 1>>>();                                                    // 5
    k_scan_write <<<SCAN_NBLK, SCAN_B>>>();                                       // 6
    k_fill       <<<N_EDGES / 256, 256>>>(ei);                                    // 7
    k_agg1mid    <<<N_NODES * 32 / 256, 256>>>(b1, W2);                           // 8
    k_agg2out    <<<N_NODES * 32 / 256, 256>>>(b2, out);                          // 9
}

// round 12
// speedup vs baseline: 1.4341x; 1.0331x over previous
#include <cuda_runtime.h>
#include <cuda_fp16.h>
#include <cstdint>

#define N_NODES 100000
#define N_EDGES 3200000
#define F_IN    300
#define HID     32
#define NCLS    10

#define SCAN_B  512
#define SCAN_NBLK ((N_NODES + SCAN_B - 1) / SCAN_B)   // 196

#define GT_ROWS 128          // gemm1 rows per block
#define GKT     40           // gemm1 k-tile (5 mma k-steps)
#define SXS     44           // sX row stride in floats - conflict-free
#define SWS     44           // sWt row stride in floats (>= GKT, padded)

// ---------------- scratch (device globals: no allocation allowed) ----------
__device__ int    g_is32;
__device__ int    g_ecnt[N_NODES];
__device__ int    g_off [N_NODES];
__device__ int    g_cur [N_NODES];
__device__ int    g_bsum[SCAN_NBLK];
__device__ float  g_dinv[N_NODES];
__device__ int    g_csr [N_EDGES];           // src only, 12.8 MB
__device__ uint4  g_h1h [N_NODES * 4];       // h1*dinv as fp16, 64B/row, 6.4 MB
__device__ uint2  g_h2h [N_NODES * 3];       // h2*dinv as fp16, 24B/row, 2.4 MB

__device__ __forceinline__ float tanh_fast(float x) {
    float y;
    asm("tanh.approx.f32 %0, %1;" : "=f"(y) : "f"(x));
    return y;
}

__device__ __forceinline__ unsigned tf32_of(float v) {
    unsigned t;
    asm("cvt.rna.tf32.f32 %0, %1;" : "=r"(t) : "f"(v));
    return t;
}

// ---------------- detect dtype + zero histogram (fused) --------------------
__global__ void k_detect_zero(const unsigned long long* __restrict__ ei) {
    int i = blockIdx.x * blockDim.x + threadIdx.x;
    if (i < N_NODES) g_ecnt[i] = 0;
    if (blockIdx.x == 0) {
        unsigned long long v = ei[threadIdx.x];
        int any = __syncthreads_or(v > 0xFFFFFFFFull ? 1 : 0);
        if (threadIdx.x == 0) g_is32 = any;
    }
}

// 4 edges per thread
__global__ void k_hist(const void* __restrict__ ei) {
    int e4 = blockIdx.x * blockDim.x + threadIdx.x;   // grid covers E/4 exactly
    if (g_is32) {
        const int4* dp = reinterpret_cast<const int4*>((const int*)ei + N_EDGES);
        int4 d = dp[e4];
        atomicAdd(&g_ecnt[d.x], 1);
        atomicAdd(&g_ecnt[d.y], 1);
        atomicAdd(&g_ecnt[d.z], 1);
        atomicAdd(&g_ecnt[d.w], 1);
    } else {
        const long long* p = (const long long*)ei;
        #pragma unroll
        for (int j = 0; j < 4; j++)
            atomicAdd(&g_ecnt[(int)p[N_EDGES + e4 * 4 + j]], 1);
    }
}

__global__ void k_dinv() {
    int i = blockIdx.x * blockDim.x + threadIdx.x;
    if (i < N_NODES) g_dinv[i] = rsqrtf((float)(g_ecnt[i] + 1));
}

// ---------------- layer-1 GEMM via tf32 tensor cores -----------------------
// Output: g_h1h[row] = (x @ W1)[row] * dinv[row], fp16.
// X operands: raw fp32 bits (HW-truncated tf32, "fast-accum" style, no cvt).
__global__ void __launch_bounds__(256)
k_gemm1(const float* __restrict__ x, const float* __restrict__ W1) {
    __shared__ uint4    sX4[GT_ROWS * (SXS / 4)];
    __shared__ unsigned sWt[HID * SWS];

    const int tid  = threadIdx.x;
    const int w    = tid >> 5;
    const int lane = tid & 31;
    const int g    = lane >> 2;     // 0..7
    const int c    = lane & 3;      // 0..3
    const int row0 = blockIdx.x * GT_ROWS;
    const int wrow = w * 16;

    const unsigned* sxu = reinterpret_cast<const unsigned*>(sX4);

    float acc[4][4];
    #pragma unroll
    for (int nt = 0; nt < 4; nt++)
        #pragma unroll
        for (int j = 0; j < 4; j++) acc[nt][j] = 0.f;

    for (int kt = 0; kt < 8; kt++) {
        const int k0 = kt * GKT;

        for (int i = tid; i < GKT * HID; i += 256) {
            int k = i >> 5, n = i & 31;
            float v = (k0 + k < F_IN) ? W1[(k0 + k) * HID + n] : 0.f;
            sWt[n * SWS + k] = tf32_of(v);
        }
        for (int i = tid; i < GT_ROWS * (GKT / 4); i += 256) {
            int r = i / (GKT / 4), cc = i % (GKT / 4);
            int row = row0 + r, col = k0 + cc * 4;
            uint4 t = make_uint4(0u, 0u, 0u, 0u);
            if (row < N_NODES && col < F_IN)
                t = *reinterpret_cast<const uint4*>(&x[(size_t)row * F_IN + col]);
            sX4[r * (SXS / 4) + cc] = t;
        }
        __syncthreads();

        #pragma unroll
        for (int ks = 0; ks < 5; ks++) {
            const int k = ks * 8;
            unsigned a0 = sxu[(wrow + g)     * SXS + k + c];
            unsigned a1 = sxu[(wrow + g + 8) * SXS + k + c];
            unsigned a2 = sxu[(wrow + g)     * SXS + k + c + 4];
            unsigned a3 = sxu[(wrow + g + 8) * SXS + k + c + 4];
            #pragma unroll
            for (int nt = 0; nt < 4; nt++) {
                unsigned b0 = sWt[(nt * 8 + g) * SWS + k + c];
                unsigned b1 = sWt[(nt * 8 + g) * SWS + k + c + 4];
                asm volatile(
                    "mma.sync.aligned.m16n8k8.row.col.f32.tf32.tf32.f32 "
                    "{%0,%1,%2,%3}, {%4,%5,%6,%7}, {%8,%9}, {%0,%1,%2,%3};"
                    : "+f"(acc[nt][0]), "+f"(acc[nt][1]),
                      "+f"(acc[nt][2]), "+f"(acc[nt][3])
                    : "r"(a0), "r"(a1), "r"(a2), "r"(a3), "r"(b0), "r"(b1));
            }
        }
        __syncthreads();
    }

    // epilogue: scale by dinv, write fp16
    __half* h1h = reinterpret_cast<__half*>(g_h1h);
    int r0i = row0 + wrow + g;
    int r1i = r0i + 8;
    float d0 = (r0i < N_NODES) ? g_dinv[r0i] : 0.f;
    float d1 = (r1i < N_NODES) ? g_dinv[r1i] : 0.f;
    #pragma unroll
    for (int nt = 0; nt < 4; nt++) {
        int col = nt * 8 + c * 2;
        if (r0i < N_NODES)
            *reinterpret_cast<__half2*>(&h1h[(size_t)r0i * HID + col]) =
                __floats2half2_rn(acc[nt][0] * d0, acc[nt][1] * d0);
        if (r1i < N_NODES)
            *reinterpret_cast<__half2*>(&h1h[(size_t)r1i * HID + col]) =
                __floats2half2_rn(acc[nt][2] * d1, acc[nt][3] * d1);
    }
}

// ---------------- scan: block sums, then write (self-computed prefix) ------
__global__ void k_scan_reduce() {
    __shared__ int s[SCAN_B];
    int i = blockIdx.x * SCAN_B + threadIdx.x;
    s[threadIdx.x] = (i < N_NODES) ? g_ecnt[i] : 0;
    __syncthreads();
    for (int d = SCAN_B / 2; d > 0; d >>= 1) {
        if (threadIdx.x < d) s[threadIdx.x] += s[threadIdx.x + d];
        __syncthreads();
    }
    if (threadIdx.x == 0) g_bsum[blockIdx.x] = s[0];
}

__global__ void k_scan_write() {
    __shared__ int s[SCAN_B];
    __shared__ int s_pre;
    const int t = threadIdx.x;

    // block prefix: sum of g_bsum[0 .. blockIdx.x)
    int partial = 0;
    for (int i = t; i < blockIdx.x; i += SCAN_B) partial += g_bsum[i];
    s[t] = partial;
    __syncthreads();
    for (int d = SCAN_B / 2; d > 0; d >>= 1) {
        if (t < d) s[t] += s[t + d];
        __syncthreads();
    }
    if (t == 0) s_pre = s[0];
    __syncthreads();
    int pre = s_pre;
    __syncthreads();

    // local inclusive scan
    int i = blockIdx.x * SCAN_B + t;
    int v = (i < N_NODES) ? g_ecnt[i] : 0;
    s[t] = v;
    __syncthreads();
    for (int d = 1; d < SCAN_B; d <<= 1) {
        int add = (t >= d) ? s[t - d] : 0;
        __syncthreads();
        s[t] += add;
        __syncthreads();
    }
    if (i < N_NODES) {
        int off = pre + s[t] - v;   // exclusive
        g_off[i] = off;
        g_cur[i] = off;
    }
}

// ---------------- CSR fill: src only, 2 edges per thread -------------------
__global__ void k_fill(const void* __restrict__ ei) {
    int e2 = blockIdx.x * blockDim.x + threadIdx.x;   // grid covers E/2 exactly
    int s0, s1, d0, d1;
    if (g_is32) {
        const int* p = (const int*)ei;
        int2 sp = reinterpret_cast<const int2*>(p)[e2];
        int2 dp = reinterpret_cast<const int2*>(p + N_EDGES)[e2];
        s0 = sp.x; s1 = sp.y; d0 = dp.x; d1 = dp.y;
    } else {
        const long long* p = (const long long*)ei;
        s0 = (int)p[e2 * 2];            s1 = (int)p[e2 * 2 + 1];
        d0 = (int)p[N_EDGES + e2 * 2];  d1 = (int)p[N_EDGES + e2 * 2 + 1];
    }
    g_csr[atomicAdd(&g_cur[d0], 1)] = s0;
    g_csr[atomicAdd(&g_cur[d1], 1)] = s1;
}

// ---------------- fused layer-1 agg + tanh + W2 GEMM -----------------------
// warp per node; lane: sub = lane&3 (uint4 chunk of 8 feats), nb = lane>>2
__global__ void k_agg1mid(const float* __restrict__ b1, const float* __restrict__ W2) {
    __shared__ float sW2[HID * NCLS];
    __shared__ float sb1[HID];
    int tid = threadIdx.x;
    for (int i = tid; i < HID * NCLS; i += 256) sW2[i] = W2[i];
    if (tid < HID) sb1[tid] = b1[tid];
    __syncthreads();

    int w    = (blockIdx.x * blockDim.x + tid) >> 5;
    int lane = tid & 31;
    int sub  = lane & 3;
    int nb   = lane >> 2;          // 0..7

    int   off = g_off[w];
    int   cnt = g_ecnt[w];
    float di  = g_dinv[w];

    float acc[8];
    #pragma unroll
    for (int j = 0; j < 8; j++) acc[j] = 0.f;

    if (nb == 0) {                 // self-loop term (already dinv-scaled)
        uint4 u = g_h1h[w * 4 + sub];
        const __half2* hp = reinterpret_cast<const __half2*>(&u);
        #pragma unroll
        for (int j = 0; j < 4; j++) {
            float2 f = __half22float2(hp[j]);
            acc[2 * j] += f.x; acc[2 * j + 1] += f.y;
        }
    }

    for (int i = nb; i < cnt; i += 8) {
        int   src = g_csr[off + i];
        uint4 u = g_h1h[src * 4 + sub];
        const __half2* hp = reinterpret_cast<const __half2*>(&u);
        #pragma unroll
        for (int j = 0; j < 4; j++) {
            float2 f = __half22float2(hp[j]);
            acc[2 * j] += f.x; acc[2 * j + 1] += f.y;
        }
    }

    #pragma unroll
    for (int m = 4; m <= 16; m <<= 1)
        #pragma unroll
        for (int j = 0; j < 8; j++)
            acc[j] += __shfl_xor_sync(0xFFFFFFFFu, acc[j], m);

    float h[8];
    #pragma unroll
    for (int j = 0; j < 8; j++)
        h[j] = tanh_fast(di * acc[j] + sb1[sub * 8 + j]);

    float p[NCLS];
    #pragma unroll
    for (int c = 0; c < NCLS; c++) {
        float s = 0.f;
        #pragma unroll
        for (int j = 0; j < 8; j++)
            s += h[j] * sW2[(sub * 8 + j) * NCLS + c];
        p[c] = s;
    }
    #pragma unroll
    for (int m = 1; m <= 2; m <<= 1)
        #pragma unroll
        for (int c = 0; c < NCLS; c++)
            p[c] += __shfl_xor_sync(0xFFFFFFFFu, p[c], m);

    if (lane == 0) {
        __half2 a = __floats2half2_rn(p[0] * di, p[1] * di);
        __half2 b = __floats2half2_rn(p[2] * di, p[3] * di);
        g_h2h[w * 3 + 0] = make_uint2(*(unsigned*)&a, *(unsigned*)&b);
    } else if (lane == 1) {
        __half2 a = __floats2half2_rn(p[4] * di, p[5] * di);
        __half2 b = __floats2half2_rn(p[6] * di, p[7] * di);
        g_h2h[w * 3 + 1] = make_uint2(*(unsigned*)&a, *(unsigned*)&b);
    } else if (lane == 2) {
        __half2 a = __floats2half2_rn(p[8] * di, p[9] * di);
        __half2 b = __floats2half2_rn(0.f, 0.f);
        g_h2h[w * 3 + 2] = make_uint2(*(unsigned*)&a, *(unsigned*)&b);
    }
}

// ---------------- fused layer-2 agg + bias + log_softmax -------------------
// warp per node; lane: nb = lane&7, sub = lane>>3 (uint2 chunk of 4 feats)
__global__ void k_agg2out(const float* __restrict__ b2, float* __restrict__ out) {
    __shared__ float sb2[NCLS];
    int tid = threadIdx.x;
    if (tid < NCLS) sb2[tid] = b2[tid];
    __syncthreads();

    int w    = (blockIdx.x * blockDim.x + tid) >> 5;
    int lane = tid & 31;
    int nb   = lane & 7;
    int sub  = lane >> 3;          // 0..3
    int csub = (sub < 3) ? sub : 2;

    int   off = g_off[w];
    int   cnt = g_ecnt[w];
    float di  = g_dinv[w];

    float acc[4];
    #pragma unroll
    for (int j = 0; j < 4; j++) acc[j] = 0.f;

    if (nb == 0 && sub < 3) {      // self-loop
        uint2 u = g_h2h[w * 3 + sub];
        float2 f0 = __half22float2(*(const __half2*)&u.x);
        float2 f1 = __half22float2(*(const __half2*)&u.y);
        acc[0] += f0.x; acc[1] += f0.y; acc[2] += f1.x; acc[3] += f1.y;
    }

    for (int i = nb; i < cnt; i += 8) {
        int   src = g_csr[off + i];
        uint2 u = g_h2h[src * 3 + csub];
        float2 f0 = __half22float2(*(const __half2*)&u.x);
        float2 f1 = __half22float2(*(const __half2*)&u.y);
        acc[0] += f0.x; acc[1] += f0.y; acc[2] += f1.x; acc[3] += f1.y;
    }

    #pragma unroll
    for (int m = 1; m <= 4; m <<= 1)
        #pragma unroll
        for (int j = 0; j < 4; j++)
            acc[j] += __shfl_xor_sync(0xFFFFFFFFu, acc[j], m);

    float v[NCLS];
    v[0] = di * __shfl_sync(0xFFFFFFFFu, acc[0], 0)  + sb2[0];
    v[1] = di * __shfl_sync(0xFFFFFFFFu, acc[1], 0)  + sb2[1];
    v[2] = di * __shfl_sync(0xFFFFFFFFu, acc[2], 0)  + sb2[2];
    v[3] = di * __shfl_sync(0xFFFFFFFFu, acc[3], 0)  + sb2[3];
    v[4] = di * __shfl_sync(0xFFFFFFFFu, acc[0], 8)  + sb2[4];
    v[5] = di * __shfl_sync(0xFFFFFFFFu, acc[1], 8)  + sb2[5];
    v[6] = di * __shfl_sync(0xFFFFFFFFu, acc[2], 8)  + sb2[6];
    v[7] = di * __shfl_sync(0xFFFFFFFFu, acc[3], 8)  + sb2[7];
    v[8] = di * __shfl_sync(0xFFFFFFFFu, acc[0], 16) + sb2[8];
    v[9] = di * __shfl_sync(0xFFFFFFFFu, acc[1], 16) + sb2[9];

    float m = v[0];
    #pragma unroll
    for (int c = 1; c < NCLS; c++) m = fmaxf(m, v[c]);
    float s = 0.f;
    #pragma unroll
    for (int c = 0; c < NCLS; c++) s += expf(v[c] - m);
    float ls = logf(s) + m;

    if (lane < NCLS) out[(size_t)w * NCLS + lane] = v[lane] - ls;
}

// ---------------- launch ---------------------------------------------------
extern "C" void kernel_launch(void* const* d_in, const int* in_sizes, int n_in,
                              void* d_out, int out_size) {
    const float* x  = (const float*)d_in[0];
    const void*  ei = d_in[1];
    const float* W1 = (const float*)d_in[2];
    const float* b1 = (const float*)d_in[3];
    const float* W2 = (const float*)d_in[4];
    const float* b2 = (const float*)d_in[5];
    float*       out = (float*)d_out;

    k_detect_zero<<<(N_NODES + 255) / 256, 256>>>((const unsigned long long*)ei); // 0
    k_hist       <<<N_EDGES / 4 / 256, 256>>>(ei);                                // 1
    k_dinv       <<<(N_NODES + 255) / 256, 256>>>();                              // 2
    k_gemm1      <<<(N_NODES + GT_ROWS - 1) / GT_ROWS, 256>>>(x, W1);             // 3 <- profiled
    k_scan_reduce<<<SCAN_NBLK, SCAN_B>>>();                                       // 4
    k_scan_write <<<SCAN_NBLK, SCAN_B>>>();                                       // 5
    k_fill       <<<N_EDGES / 2 / 256, 256>>>(ei);                                // 6
    k_agg1mid    <<<N_NODES * 32 / 256, 256>>>(b1, W2);                           // 7
    k_agg2out    <<<N_NODES * 32 / 256, 256>>>(b2, out);                          // 8
}